// round 14
// baseline (speedup 1.0000x reference)
#include <cuda_runtime.h>
#include <cuda_fp16.h>
#include <cstdint>
#include <cstddef>

#define NB   32
#define HWD  56
#define CIN  128
#define OC   256
#define NPIX (NB*HWD*HWD)   // 100352
#define KW   1152           // 9*128

// scratch (no runtime allocation allowed)
__device__ __align__(16) __half g_x16[(size_t)NPIX * CIN]; // NHWC fp16 (exact ints)
__device__ __align__(16) __half g_w16[(size_t)OC * KW];    // [oc][(r*3+s)*128+c]

__device__ __forceinline__ uint32_t smem_u32(const void* p) {
    uint32_t a;
    asm("{ .reg .u64 t; cvta.to.shared.u64 t, %1; cvt.u32.u64 %0, t; }"
        : "=r"(a) : "l"(p));
    return a;
}
#define CPA16(dst, src, sz) \
    asm volatile("cp.async.cg.shared.global [%0], [%1], 16, %2;" \
                 :: "r"(dst), "l"(src), "r"(sz))
#define CPA_COMMIT() asm volatile("cp.async.commit_group;")

__device__ __forceinline__ void ldsm4(uint32_t& r0, uint32_t& r1, uint32_t& r2,
                                      uint32_t& r3, uint32_t addr) {
    asm volatile("ldmatrix.sync.aligned.m8n8.x4.shared.b16 {%0,%1,%2,%3}, [%4];"
                 : "=r"(r0), "=r"(r1), "=r"(r2), "=r"(r3) : "r"(addr));
}

// ---------------------------------------------------------------------------
// Fused prep: blocks [0,1792) = x (fp32 NCHW -> fp16 NHWC); rest = weights.
// ---------------------------------------------------------------------------
#define XBLKS (NB * HWD)                       // 1792
#define WBLKS ((OC * KW) / 256)                // 1152

__global__ void prep_fused(const float* __restrict__ x,
                           const float* __restrict__ wt) {
    const int tid = threadIdx.x;

    if (blockIdx.x >= XBLKS) {
        int i = (blockIdx.x - XBLKS) * 256 + tid;
        int oc = i / KW, k = i - oc * KW;
        int rs = k >> 7, c = k & 127;
        int r = rs / 3, s = rs - r * 3;
        float v = wt[(((size_t)oc * CIN + c) * 3 + r) * 3 + s];
        g_w16[i] = __float2half_rn((float)(int)v);
        return;
    }

    __shared__ __half t[56 * 132];
    int n = blockIdx.x / 56, h = blockIdx.x - n * 56;
    const float* src = x + (size_t)n * CIN * 3136 + h * 56;

    int c = tid / 56, w = tid - c * 56;
#pragma unroll
    for (int i = 0; i < 28; i++) {
        float v = src[(size_t)c * 3136 + w];
        t[w * 132 + c] = __float2half_rn((float)(int)v);  // trunc == jnp.trunc
        w += 32; c += 4;
        if (w >= 56) { w -= 56; c += 1; }
    }
    __syncthreads();

    uint2* go = (uint2*)(g_x16 + (size_t)blockIdx.x * 56 * 128);
#pragma unroll
    for (int i = 0; i < 7; i++) {
        int widx = i * 256 + tid;
        int ww = widx >> 5, c4 = widx & 31;
        go[widx] = *(const uint2*)&t[ww * 132 + c4 * 4];
    }
}

// ---------------------------------------------------------------------------
// Main kernel: implicit GEMM via mma.sync m16n8k16 f16 (f32 accum).
// CTA tile 128 pix x 128 oc; 256 threads, 8 warps = 2(M) x 4(N),
// warp tile 64 x 32 (acc 64 regs). K = 18 stages of 64 channels;
// 3-buffer cp.async, 96KB smem, 2 CTAs/SM. 128-reg budget enables
// double-buffered ldmatrix fragments: LDSM(k+1) issued before MMA(k).
// ---------------------------------------------------------------------------
#define ASZ    16384                // 128 rows x 128 B (64 halves)
#define STG_SZ 32768                // A + B
#define SMEM_TOTAL (3 * STG_SZ)     // 98304

__global__ void __launch_bounds__(256, 2) qconv(
    const float* __restrict__ bias, const int* __restrict__ Aq,
    const int* __restrict__ Nq, const int* __restrict__ pmin,
    const int* __restrict__ pmax, float* __restrict__ out)
{
    extern __shared__ __align__(128) signed char smem[];
    const uint32_t sb = smem_u32(smem);

    const int tid  = threadIdx.x;
    const int lane = tid & 31, wid = tid >> 5;
    const int gid  = lane >> 2, tg = lane & 3;
    const int warp_m = wid >> 2, warp_n = wid & 3;       // 2 x 4
    const int p0  = blockIdx.x * 128;
    const int oc0 = blockIdx.y * 128;

    // loader: thread -> (row = tid>>1, halfA = tid&1), 4 x 16B chunks / operand
    const int row = tid >> 1, halfA = tid & 1;
    const int p = p0 + row;
    const int n = p / 3136, rem = p - n * 3136;
    const int h = rem / 56, w = rem - h * 56;
    const __half* abase = g_x16 + (size_t)p * CIN + halfA * 32;
    const __half* bbase = g_w16 + (size_t)(oc0 + row) * KW + halfA * 32;
    uint32_t soff[4];
#pragma unroll
    for (int j = 0; j < 4; j++)
        soff[j] = (uint32_t)row * 128 +
                  ((uint32_t)((halfA * 4 + j) ^ (row & 7)) << 4);

    // stage s (0..17): tap = s>>1, channel half = s&1
    auto load_stage = [&](int buf, int s) {
        const int tap = s >> 1, ch = s & 1;
        const int rr = tap / 3, ss = tap - rr * 3;
        const int y = h + rr - 1, xx = w + ss - 1;
        const bool ok = ((unsigned)y < 56u) && ((unsigned)xx < 56u);
        const int sz = ok ? 16 : 0;
        const __half* asrc = (ok ? abase + ((rr - 1) * 56 + (ss - 1)) * CIN : abase)
                             + ch * 64;
        const __half* bsrc = bbase + s * 64;
        const uint32_t da = sb + buf * STG_SZ;
        const uint32_t db = da + ASZ;
#pragma unroll
        for (int j = 0; j < 4; j++) {
            CPA16(da + soff[j], asrc + j * 8, sz);
            CPA16(db + soff[j], bsrc + j * 8, 16);
        }
    };

    float acc[4][4][4];
#pragma unroll
    for (int a = 0; a < 4; a++)
#pragma unroll
        for (int b = 0; b < 4; b++)
#pragma unroll
            for (int c = 0; c < 4; c++) acc[a][b][c] = 0.0f;

    const int lrow = lane & 15;
    const int lhi  = lane >> 4;

    // double-buffered fragments
    uint32_t af[2][4][4];    // [pb][mt][4]
    uint32_t bf[2][4][2];    // [pb][nt][2]

    // ldsm one k16-step into fragment buffer pb (k = 0..3 within stage)
    auto ldsm_step = [&](int pb, uint32_t As, uint32_t Bs, int k) {
#pragma unroll
        for (int bt = 0; bt < 2; bt++) {
            int r = warp_n * 32 + bt * 16 + lrow;
            uint32_t addr = Bs + (uint32_t)r * 128 +
                            ((uint32_t)((2 * k + lhi) ^ (r & 7)) << 4);
            ldsm4(bf[pb][bt * 2][0], bf[pb][bt * 2 + 1][0],
                  bf[pb][bt * 2][1], bf[pb][bt * 2 + 1][1], addr);
        }
#pragma unroll
        for (int mt = 0; mt < 4; mt++) {
            int r = warp_m * 64 + mt * 16 + lrow;
            uint32_t addr = As + (uint32_t)r * 128 +
                            ((uint32_t)((2 * k + lhi) ^ (r & 7)) << 4);
            ldsm4(af[pb][mt][0], af[pb][mt][1], af[pb][mt][2], af[pb][mt][3], addr);
        }
    };
    auto mma_step = [&](int pb) {
#pragma unroll
        for (int mt = 0; mt < 4; mt++)
#pragma unroll
            for (int nt = 0; nt < 4; nt++) {
                asm volatile(
                    "mma.sync.aligned.m16n8k16.row.col.f32.f16.f16.f32 "
                    "{%0,%1,%2,%3}, {%4,%5,%6,%7}, {%8,%9}, {%0,%1,%2,%3};\n"
                    : "+f"(acc[mt][nt][0]), "+f"(acc[mt][nt][1]),
                      "+f"(acc[mt][nt][2]), "+f"(acc[mt][nt][3])
                    : "r"(af[pb][mt][0]), "r"(af[pb][mt][1]),
                      "r"(af[pb][mt][2]), "r"(af[pb][mt][3]),
                      "r"(bf[pb][nt][0]), "r"(bf[pb][nt][1]));
            }
    };

    load_stage(0, 0); CPA_COMMIT();
    load_stage(1, 1); CPA_COMMIT();

    for (int s = 0; s < 18; s++) {
        const int buf = s % 3;
        asm volatile("cp.async.wait_group 1;");
        __syncthreads();

        if (s + 2 < 18) load_stage((s + 2) % 3, s + 2);
        CPA_COMMIT();

        const uint32_t As = sb + buf * STG_SZ;
        const uint32_t Bs = As + ASZ;

        // software-pipelined k-steps: LDSM(k+1) issued before MMA(k)
        ldsm_step(0, As, Bs, 0);
#pragma unroll
        for (int k = 0; k < 4; k++) {
            if (k < 3) ldsm_step((k + 1) & 1, As, Bs, k + 1);
            mma_step(k & 1);
        }
        __syncthreads();
    }

    // ---- epilogue: bias + requant + round + clip, sector-coalesced STG ----
    const int omin = *pmin, omax = *pmax;
    const float fmin = (float)omin, fmax = (float)omax;
    float bj[4][2], sc[4][2];
#pragma unroll
    for (int nt = 0; nt < 4; nt++)
#pragma unroll
        for (int j = 0; j < 2; j++) {
            int oc = oc0 + warp_n * 32 + nt * 8 + tg * 2 + j;
            bj[nt][j] = __ldg(&bias[oc]);
            // A * 2^-N exact (N in [16,25) -> normal exponent); single rounding
            float p2 = __int_as_float((127 - __ldg(&Nq[oc])) << 23);
            sc[nt][j] = (float)__ldg(&Aq[oc]) * p2;
        }

#pragma unroll
    for (int mt = 0; mt < 4; mt++) {
#pragma unroll
        for (int hfl = 0; hfl < 2; hfl++) {
            int pix = p0 + warp_m * 64 + mt * 16 + gid + 8 * hfl;
            int n2 = pix / 3136; int rem2 = pix - n2 * 3136;
            float* ob = out + (size_t)n2 * OC * 3136 + rem2;
#pragma unroll
            for (int nt = 0; nt < 4; nt++) {
#pragma unroll
                for (int j = 0; j < 2; j++) {
                    int oc = oc0 + warp_n * 32 + nt * 8 + tg * 2 + j;
                    float f = (acc[mt][nt][hfl * 2 + j] + bj[nt][j]) * sc[nt][j];
                    if (omin >= 0) {
                        f = rintf(f);                    // half-to-even == jnp.round
                        f = fminf(fmaxf(f, fmin), fmax);
                    }
                    ob[(size_t)oc * 3136] = f;
                }
            }
        }
    }
}

// ---------------------------------------------------------------------------
// Launch. Inputs: x, weight_int, bias_int, A, N, out_min, out_max
// ---------------------------------------------------------------------------
extern "C" void kernel_launch(void* const* d_in, const int* in_sizes, int n_in,
                              void* d_out, int out_size) {
    const float* x    = (const float*)d_in[0];
    const float* wt   = (const float*)d_in[1];
    const float* bias = (const float*)d_in[2];
    const int*   Aq   = (const int*)d_in[3];
    const int*   Nq   = (const int*)d_in[4];
    const int*   omin = (const int*)d_in[5];
    const int*   omax = (const int*)d_in[6];
    float* out = (float*)d_out;

    static int configured = 0;
    if (!configured) {
        cudaFuncSetAttribute(qconv, cudaFuncAttributeMaxDynamicSharedMemorySize,
                             SMEM_TOTAL);
        configured = 1;
    }

    prep_fused<<<XBLKS + WBLKS, 256>>>(x, wt);
    dim3 grid(NPIX / 128, OC / 128);
    qconv<<<grid, 256, SMEM_TOTAL>>>(bias, Aq, Nq, omin, omax, out);
}

// round 15
// speedup vs baseline: 1.2111x; 1.2111x over previous
#include <cuda_runtime.h>
#include <cuda_fp16.h>
#include <cstdint>
#include <cstddef>

#define NB   32
#define HWD  56
#define CIN  128
#define OC   256
#define NPIX (NB*HWD*HWD)   // 100352
#define KW   1152           // 9*128

// scratch (no runtime allocation allowed)
__device__ __align__(16) __half g_x16[(size_t)NPIX * CIN]; // NHWC fp16 (exact ints)
__device__ __align__(16) __half g_w16[(size_t)OC * KW];    // [oc][(r*3+s)*128+c]

__device__ __forceinline__ uint32_t smem_u32(const void* p) {
    uint32_t a;
    asm("{ .reg .u64 t; cvta.to.shared.u64 t, %1; cvt.u32.u64 %0, t; }"
        : "=r"(a) : "l"(p));
    return a;
}
#define CPA16(dst, src, sz) \
    asm volatile("cp.async.cg.shared.global [%0], [%1], 16, %2;" \
                 :: "r"(dst), "l"(src), "r"(sz))
#define CPA_COMMIT() asm volatile("cp.async.commit_group;")

__device__ __forceinline__ void ldsm4(uint32_t& r0, uint32_t& r1, uint32_t& r2,
                                      uint32_t& r3, uint32_t addr) {
    asm volatile("ldmatrix.sync.aligned.m8n8.x4.shared.b16 {%0,%1,%2,%3}, [%4];"
                 : "=r"(r0), "=r"(r1), "=r"(r2), "=r"(r3) : "r"(addr));
}

// ---------------------------------------------------------------------------
// Fused prep: blocks [0,1792) = x (fp32 NCHW -> fp16 NHWC); rest = weights.
// ---------------------------------------------------------------------------
#define XBLKS (NB * HWD)                       // 1792
#define WBLKS ((OC * KW) / 256)                // 1152

__global__ void prep_fused(const float* __restrict__ x,
                           const float* __restrict__ wt) {
    const int tid = threadIdx.x;

    if (blockIdx.x >= XBLKS) {
        int i = (blockIdx.x - XBLKS) * 256 + tid;
        int oc = i / KW, k = i - oc * KW;
        int rs = k >> 7, c = k & 127;
        int r = rs / 3, s = rs - r * 3;
        float v = wt[(((size_t)oc * CIN + c) * 3 + r) * 3 + s];
        g_w16[i] = __float2half_rn((float)(int)v);
        return;
    }

    __shared__ __half t[56 * 132];
    int n = blockIdx.x / 56, h = blockIdx.x - n * 56;
    const float* src = x + (size_t)n * CIN * 3136 + h * 56;

    int c = tid / 56, w = tid - c * 56;
#pragma unroll
    for (int i = 0; i < 28; i++) {
        float v = src[(size_t)c * 3136 + w];
        t[w * 132 + c] = __float2half_rn((float)(int)v);  // trunc == jnp.trunc
        w += 32; c += 4;
        if (w >= 56) { w -= 56; c += 1; }
    }
    __syncthreads();

    uint2* go = (uint2*)(g_x16 + (size_t)blockIdx.x * 56 * 128);
#pragma unroll
    for (int i = 0; i < 7; i++) {
        int widx = i * 256 + tid;
        int ww = widx >> 5, c4 = widx & 31;
        go[widx] = *(const uint2*)&t[ww * 132 + c4 * 4];
    }
}

// ---------------------------------------------------------------------------
// Main kernel: implicit GEMM via mma.sync m16n8k16 f16 (f32 accum).
// CTA tile 128 pix x 128 oc; 512 threads, 16 warps = 4(M) x 4(N),
// warp tile 32 x 32 (acc 32 regs). K = 18 stages of 64 channels;
// 3-buffer cp.async, 96KB smem, 2 CTAs/SM = 8 warps/SMSP.
// Single sync per stage; XOR-incremental ldmatrix addressing
// (addr(k) = addr(0) ^ (k<<5), exact identity of the swizzle).
// ---------------------------------------------------------------------------
#define ASZ    16384                // 128 rows x 128 B (64 halves)
#define STG_SZ 32768                // A + B
#define SMEM_TOTAL (3 * STG_SZ)     // 98304

__global__ void __launch_bounds__(512, 2) qconv(
    const float* __restrict__ bias, const int* __restrict__ Aq,
    const int* __restrict__ Nq, const int* __restrict__ pmin,
    const int* __restrict__ pmax, float* __restrict__ out)
{
    extern __shared__ __align__(128) signed char smem[];
    const uint32_t sb = smem_u32(smem);

    const int tid  = threadIdx.x;
    const int lane = tid & 31, wid = tid >> 5;
    const int gid  = lane >> 2, tg = lane & 3;
    const int warp_m = wid >> 2, warp_n = wid & 3;       // 4 x 4
    const int p0  = blockIdx.x * 128;
    const int oc0 = blockIdx.y * 128;

    // loader: 512 threads, thread -> (row = tid>>2, q = tid&3), 2 chunks each op
    const int row = tid >> 2, q = tid & 3;
    const int p = p0 + row;
    const int n = p / 3136, rem = p - n * 3136;
    const int h = rem / 56, w = rem - h * 56;
    const __half* abase = g_x16 + (size_t)p * CIN;
    const __half* bbase = g_w16 + (size_t)(oc0 + row) * KW;
    uint32_t soff[2];
#pragma unroll
    for (int j = 0; j < 2; j++)
        soff[j] = (uint32_t)row * 128 +
                  ((uint32_t)((q * 2 + j) ^ (row & 7)) << 4);

    // stage s (0..17): tap = s>>1, channel half = s&1
    auto load_stage = [&](int buf, int s) {
        const int tap = s >> 1, ch = s & 1;
        const int rr = tap / 3, ss = tap - rr * 3;
        const int y = h + rr - 1, xx = w + ss - 1;
        const bool ok = ((unsigned)y < 56u) && ((unsigned)xx < 56u);
        const int sz = ok ? 16 : 0;
        const __half* asrc = (ok ? abase + ((rr - 1) * 56 + (ss - 1)) * CIN : abase)
                             + ch * 64;
        const __half* bsrc = bbase + s * 64;
        const uint32_t da = sb + buf * STG_SZ;
        const uint32_t db = da + ASZ;
#pragma unroll
        for (int j = 0; j < 2; j++) {
            CPA16(da + soff[j], asrc + (q * 2 + j) * 8, sz);
            CPA16(db + soff[j], bsrc + (q * 2 + j) * 8, 16);
        }
    };

    float acc[2][4][4];
#pragma unroll
    for (int a = 0; a < 2; a++)
#pragma unroll
        for (int b = 0; b < 4; b++)
#pragma unroll
            for (int c = 0; c < 4; c++) acc[a][b][c] = 0.0f;

    const int lrow = lane & 15;          // row within 16-row tile
    const int lhi  = lane >> 4;          // chunk select for matrices 2,3

    // per-warp k=0 address offsets within a stage buffer (swizzled);
    // addr(k) = addr(0) ^ (k << 5)   [exact: chunk(k) = chunk(0) ^ 2k]
    uint32_t offB[2], offA[2];
#pragma unroll
    for (int bt = 0; bt < 2; bt++) {
        int r = warp_n * 32 + bt * 16 + lrow;
        offB[bt] = ASZ + (uint32_t)r * 128 + ((uint32_t)(lhi ^ (r & 7)) << 4);
    }
#pragma unroll
    for (int mt = 0; mt < 2; mt++) {
        int r = warp_m * 32 + mt * 16 + lrow;
        offA[mt] = (uint32_t)r * 128 + ((uint32_t)(lhi ^ (r & 7)) << 4);
    }

    load_stage(0, 0); CPA_COMMIT();
    load_stage(1, 1); CPA_COMMIT();

    int buf = 0;
    for (int s = 0; s < 18; s++) {
        asm volatile("cp.async.wait_group 1;");
        __syncthreads();                 // data(s) visible; all warps done s-1

        if (s + 2 < 18) {
            int nb = buf + 2; if (nb >= 3) nb -= 3;
            load_stage(nb, s + 2);       // overwrites buf (s-1)%3: safe post-sync
        }
        CPA_COMMIT();

        const uint32_t base = sb + buf * STG_SZ;
#pragma unroll
        for (int k = 0; k < 4; k++) {    // addr = base + off ^ (k<<5)
            uint32_t bf[4][2];
#pragma unroll
            for (int bt = 0; bt < 2; bt++) {
                ldsm4(bf[bt * 2][0], bf[bt * 2 + 1][0],
                      bf[bt * 2][1], bf[bt * 2 + 1][1],
                      base + (offB[bt] ^ (k << 5)));
            }
#pragma unroll
            for (int mt = 0; mt < 2; mt++) {
                uint32_t a0, a1, a2, a3;
                ldsm4(a0, a1, a2, a3, base + (offA[mt] ^ (k << 5)));
#pragma unroll
                for (int nt = 0; nt < 4; nt++) {
                    asm volatile(
                        "mma.sync.aligned.m16n8k16.row.col.f32.f16.f16.f32 "
                        "{%0,%1,%2,%3}, {%4,%5,%6,%7}, {%8,%9}, {%0,%1,%2,%3};\n"
                        : "+f"(acc[mt][nt][0]), "+f"(acc[mt][nt][1]),
                          "+f"(acc[mt][nt][2]), "+f"(acc[mt][nt][3])
                        : "r"(a0), "r"(a1), "r"(a2), "r"(a3),
                          "r"(bf[nt][0]), "r"(bf[nt][1]));
                }
            }
        }
        buf++; if (buf >= 3) buf -= 3;
    }

    // ---- epilogue: bias + requant + round + clip, sector-coalesced STG ----
    const int omin = *pmin, omax = *pmax;
    const float fmin = (float)omin, fmax = (float)omax;
    float bj[4][2], sc[4][2];
#pragma unroll
    for (int nt = 0; nt < 4; nt++)
#pragma unroll
        for (int j = 0; j < 2; j++) {
            int oc = oc0 + warp_n * 32 + nt * 8 + tg * 2 + j;
            bj[nt][j] = __ldg(&bias[oc]);
            // A * 2^-N exact (N in [16,25) -> normal exponent); single rounding
            float p2 = __int_as_float((127 - __ldg(&Nq[oc])) << 23);
            sc[nt][j] = (float)__ldg(&Aq[oc]) * p2;
        }

#pragma unroll
    for (int mt = 0; mt < 2; mt++) {
#pragma unroll
        for (int hfl = 0; hfl < 2; hfl++) {
            int pix = p0 + warp_m * 32 + mt * 16 + gid + 8 * hfl;
            int n2 = pix / 3136; int rem2 = pix - n2 * 3136;
            float* ob = out + (size_t)n2 * OC * 3136 + rem2;
#pragma unroll
            for (int nt = 0; nt < 4; nt++) {
#pragma unroll
                for (int j = 0; j < 2; j++) {
                    int oc = oc0 + warp_n * 32 + nt * 8 + tg * 2 + j;
                    float f = (acc[mt][nt][hfl * 2 + j] + bj[nt][j]) * sc[nt][j];
                    if (omin >= 0) {
                        f = rintf(f);                    // half-to-even == jnp.round
                        f = fminf(fmaxf(f, fmin), fmax);
                    }
                    ob[(size_t)oc * 3136] = f;
                }
            }
        }
    }
}

// ---------------------------------------------------------------------------
// Launch. Inputs: x, weight_int, bias_int, A, N, out_min, out_max
// ---------------------------------------------------------------------------
extern "C" void kernel_launch(void* const* d_in, const int* in_sizes, int n_in,
                              void* d_out, int out_size) {
    const float* x    = (const float*)d_in[0];
    const float* wt   = (const float*)d_in[1];
    const float* bias = (const float*)d_in[2];
    const int*   Aq   = (const int*)d_in[3];
    const int*   Nq   = (const int*)d_in[4];
    const int*   omin = (const int*)d_in[5];
    const int*   omax = (const int*)d_in[6];
    float* out = (float*)d_out;

    static int configured = 0;
    if (!configured) {
        cudaFuncSetAttribute(qconv, cudaFuncAttributeMaxDynamicSharedMemorySize,
                             SMEM_TOTAL);
        configured = 1;
    }

    prep_fused<<<XBLKS + WBLKS, 256>>>(x, wt);
    dim3 grid(NPIX / 128, OC / 128);
    qconv<<<grid, 512, SMEM_TOTAL>>>(bias, Aq, Nq, omin, omax, out);
}